// round 10
// baseline (speedup 1.0000x reference)
#include <cuda_runtime.h>
#include <utility>

#define HH 256
#define WW 256
#define BB 16
#define CIN 32
#define COUT 32
#define KM 16

// Partial-S handoff: k1 writes per-h-half partial sums, k23 adds both.
__device__ float g_SreP[2][BB * CIN * KM], g_SimP[2][BB * CIN * KM];

// Packed f32x2 FMA: d = a*b + c elementwise on {lo,hi} fp32 pairs (FFMA2)
#define FMA2(d, a, b, c) \
    asm("fma.rn.f32x2 %0, %1, %2, %3;" : "=l"(d) : "l"(a), "l"(b), "l"(c))

__device__ __forceinline__ unsigned long long pack2(float lo, float hi) {
    unsigned long long d;
    asm("mov.b64 %0, {%1, %2};" : "=l"(d) : "f"(lo), "f"(hi));
    return d;
}
__device__ __forceinline__ void unpack2(unsigned long long v, float& lo, float& hi) {
    asm("mov.b64 {%0, %1}, %2;" : "=f"(lo), "=f"(hi) : "l"(v));
}

// ---------------------------------------------------------------------------
// Compile-time trig: cos/sin(pi*m/128), exact integer range reduction +
// deg-15/14 Taylor (err ~1e-11). Become FFMA 32-bit immediates.
// ---------------------------------------------------------------------------
constexpr __host__ __device__ double tp_sin(double x) {
    double x2 = x * x, t = x, s = x;
    t *= -x2 / 6.0;   s += t;
    t *= -x2 / 20.0;  s += t;
    t *= -x2 / 42.0;  s += t;
    t *= -x2 / 72.0;  s += t;
    t *= -x2 / 110.0; s += t;
    t *= -x2 / 156.0; s += t;
    t *= -x2 / 210.0; s += t;
    return s;
}
constexpr __host__ __device__ double tp_cos(double x) {
    double x2 = x * x, t = 1.0, s = 1.0;
    t *= -x2 / 2.0;   s += t;
    t *= -x2 / 12.0;  s += t;
    t *= -x2 / 30.0;  s += t;
    t *= -x2 / 56.0;  s += t;
    t *= -x2 / 90.0;  s += t;
    t *= -x2 / 132.0; s += t;
    t *= -x2 / 182.0; s += t;
    return s;
}
constexpr double C_PI = 3.14159265358979323846264338327950288;

constexpr __host__ __device__ float ccosm(int m) {   // cos(pi*m/128)
    m &= 255;
    double sgn = 1.0;
    if (m > 128) m = 256 - m;
    if (m > 64) { sgn = -1.0; m = 128 - m; }
    if (m == 64) return 0.0f;
    return (float)(sgn * tp_cos(C_PI * m / 128.0));
}
constexpr __host__ __device__ float csinm(int m) {   // sin(pi*m/128)
    m &= 255;
    double sgn = 1.0;
    if (m > 128) { sgn = -1.0; m = 256 - m; }
    if (m > 64) m = 128 - m;
    if (m == 0) return 0.0f;
    return (float)(sgn * tp_sin(C_PI * m / 128.0));
}
constexpr __host__ __device__ float cDr(int h) {   // Re D(h)
    double s = 0.0;
    for (int r = 0; r < KM; r++) s += (double)ccosm(r * h);
    return (float)s;
}
constexpr __host__ __device__ float cDi(int h) {   // Im D(h)
    double s = 0.0;
    for (int r = 0; r < KM; r++) s -= (double)csinm(r * h);
    return (float)s;
}

// ---------------------------------------------------------------------------
// K1 (h-split): block = (bc, half). Covers rows [half*128, half*128+128).
//   thread (q = t&63, stripe = t>>6) loads float4 at column 4q, rows
//   h = half*128 + stripe + 4*j, j<32.  D(h) as FFMA immediates.
//   Column-DFT on the PARTIAL y (linear), result to g_S*P[half].
// ---------------------------------------------------------------------------
template <int H>
__device__ __forceinline__ void k1s_one(const float4* __restrict__ xq, float* acc) {
    float4 v = xq[H * (WW / 4)];
    constexpr float dr = cDr(H);
    constexpr float di = cDi(H);
    acc[0] = fmaf(v.x, dr, acc[0]);  acc[1] = fmaf(v.x, di, acc[1]);
    acc[2] = fmaf(v.y, dr, acc[2]);  acc[3] = fmaf(v.y, di, acc[3]);
    acc[4] = fmaf(v.z, dr, acc[4]);  acc[5] = fmaf(v.z, di, acc[5]);
    acc[6] = fmaf(v.w, dr, acc[6]);  acc[7] = fmaf(v.w, di, acc[7]);
}
template <int BASE, int... Js>
__device__ __forceinline__ void k1s_all(const float4* __restrict__ xq, float* acc,
                                        std::integer_sequence<int, Js...>) {
    (k1s_one<BASE + 4 * Js>(xq, acc), ...);
}

__global__ __launch_bounds__(256) void k1_S(const float* __restrict__ x) {
    int blk  = blockIdx.x;
    int bc   = blk >> 1;          // b*CIN + c
    int half = blk & 1;
    int t    = threadIdx.x;       // 0..255
    int q      = t & 63;          // float4 column
    int stripe = t >> 6;          // 0..3

    __shared__ float2 spart[4 * WW];      // [stripe][w] {yre,yim}
    __shared__ float  syre[WW], syim[WW];

    const float4* xq = reinterpret_cast<const float4*>(x + (size_t)bc * HH * WW) + q;
    float acc[8] = {0.f, 0.f, 0.f, 0.f, 0.f, 0.f, 0.f, 0.f};
    using Seq = std::make_integer_sequence<int, 32>;
    switch ((half << 2) | stripe) {
        case 0: k1s_all<0>(xq, acc, Seq{});   break;
        case 1: k1s_all<1>(xq, acc, Seq{});   break;
        case 2: k1s_all<2>(xq, acc, Seq{});   break;
        case 3: k1s_all<3>(xq, acc, Seq{});   break;
        case 4: k1s_all<128>(xq, acc, Seq{}); break;
        case 5: k1s_all<129>(xq, acc, Seq{}); break;
        case 6: k1s_all<130>(xq, acc, Seq{}); break;
        default: k1s_all<131>(xq, acc, Seq{}); break;
    }
#pragma unroll
    for (int e = 0; e < 4; e++)
        spart[stripe * WW + 4 * q + e] = make_float2(acc[2 * e], acc[2 * e + 1]);
    __syncthreads();

    {
        int w = t;
        float2 a = spart[0 * WW + w], b2 = spart[1 * WW + w];
        float2 c = spart[2 * WW + w], d2 = spart[3 * WW + w];
        syre[w] = (a.x + b2.x) + (c.x + d2.x);
        syim[w] = (a.y + b2.y) + (c.y + d2.y);
    }
    __syncthreads();

    // 8 warps, each warp handles cols {warp, warp+8}; twiddles on the fly
    int warp = t >> 5, lane = t & 31;
    for (int cc = warp; cc < KM; cc += 8) {
        float are = 0.f, aim = 0.f;
#pragma unroll
        for (int it = 0; it < 8; it++) {
            int j = lane + it * 32;
            float s, c;
            sincospif((float)(cc * j) / 128.0f, &s, &c);
            float yr = syre[j], yi = syim[j];
            are = fmaf(yr, c, are);  are = fmaf(yi, s, are);
            aim = fmaf(yi, c, aim);  aim = fmaf(-yr, s, aim);
        }
#pragma unroll
        for (int off = 16; off; off >>= 1) {
            are += __shfl_down_sync(0xffffffffu, are, off);
            aim += __shfl_down_sync(0xffffffffu, aim, off);
        }
        if (lane == 0) {
            g_SreP[half][bc * KM + cc] = are * (1.0f / 256.0f);
            g_SimP[half][bc * KM + cc] = aim * (1.0f / 256.0f);
        }
    }
}

// ---------------------------------------------------------------------------
// K23 phase C, dual-w: for one h-group compute out for w0 and w1 as two
// independent scalar FFMA-immediate chains, pack pairs, store STG.64.
// ---------------------------------------------------------------------------
template <int H, int R>
__device__ __forceinline__ void k3_step2(const float* pre0, const float* pim0,
                                         const float* pre1, const float* pim1,
                                         float& Ae0, float& Ao0, float& Be0, float& Bo0,
                                         float& Ae1, float& Ao1, float& Be1, float& Bo1) {
    constexpr float cv = ccosm(R * H);
    constexpr float sv = csinm(R * H);
    if constexpr ((R & 1) != 0) {
        if constexpr (cv != 0.0f) { Ao0 = fmaf(pre0[R], cv, Ao0); Ao1 = fmaf(pre1[R], cv, Ao1); }
        if constexpr (sv != 0.0f) { Bo0 = fmaf(pim0[R], sv, Bo0); Bo1 = fmaf(pim1[R], sv, Bo1); }
    } else {
        if constexpr (cv != 0.0f) { Ae0 = fmaf(pre0[R], cv, Ae0); Ae1 = fmaf(pre1[R], cv, Ae1); }
        if constexpr (sv != 0.0f) { Be0 = fmaf(pim0[R], sv, Be0); Be1 = fmaf(pim1[R], sv, Be1); }
    }
}
template <int H, int... Rs>
__device__ __forceinline__ void k3_one2(const float* pre0, const float* pim0,
                                        const float* pre1, const float* pim1,
                                        unsigned long long* __restrict__ op64,
                                        std::integer_sequence<int, Rs...>) {
    float Ae0 = 0.f, Ao0 = 0.f, Be0 = 0.f, Bo0 = 0.f;
    float Ae1 = 0.f, Ao1 = 0.f, Be1 = 0.f, Bo1 = 0.f;
    (k3_step2<H, Rs>(pre0, pim0, pre1, pim1,
                     Ae0, Ao0, Be0, Bo0, Ae1, Ao1, Be1, Bo1), ...);
    float Apl0 = Ae0 + Ao0, Ami0 = Ae0 - Ao0, Bpl0 = Be0 + Bo0, Bmi0 = Be0 - Bo0;
    float Apl1 = Ae1 + Ao1, Ami1 = Ae1 - Ao1, Bpl1 = Be1 + Bo1, Bmi1 = Be1 - Bo1;
    op64[(size_t)H * (WW / 2)] = pack2(Apl0 - Bpl0, Apl1 - Bpl1);
    if constexpr (H != 64)
        op64[(size_t)(128 - H) * (WW / 2)] = pack2(Ami0 + Bmi0, Ami1 + Bmi1);
    if constexpr (H >= 1)
        op64[(size_t)(256 - H) * (WW / 2)] = pack2(Apl0 + Bpl0, Apl1 + Bpl1);
    if constexpr (H >= 1 && H != 64)
        op64[(size_t)(128 + H) * (WW / 2)] = pack2(Ami0 - Bmi0, Ami1 - Bmi1);
}
template <int... Hs>
__device__ __forceinline__ void k3_all2(const float* pre0, const float* pim0,
                                        const float* pre1, const float* pim1,
                                        unsigned long long* __restrict__ op64,
                                        std::integer_sequence<int, Hs...>) {
    (k3_one2<Hs>(pre0, pim0, pre1, pim1, op64,
                 std::make_integer_sequence<int, KM>{}), ...);
}

// ---------------------------------------------------------------------------
// K23 (fused, w-paired): block = bo, 128 threads; thread t owns w0=2t, w1=2t+1.
//   Phase A: blk[r,c] (sums both k1 partial-S halves on load).
//   Phase B: two packed {ReP,ImP} sets; one LDS.128 of blk serves both w.
//   Phase C: dual scalar immediate-trig chains; STG.64 paired stores.
// ---------------------------------------------------------------------------
__global__ __launch_bounds__(128, 4) void k23(const float* __restrict__ wr,
                                              const float* __restrict__ wi,
                                              float* __restrict__ out) {
    int bo = blockIdx.x;           // b*COUT + o
    int b = bo >> 5, o = bo & 31;
    int t = threadIdx.x;           // 0..127

    __shared__ float  sSre[CIN * KM], sSim[CIN * KM];  // [i][r]
    __shared__ float4 sBq[KM * KM];                    // [r][c] {bre,bre,-bim,bim}

    for (int idx = t; idx < CIN * KM; idx += 128) {
        int off = b * CIN * KM + idx;
        sSre[idx] = g_SreP[0][off] + g_SreP[1][off];
        sSim[idx] = g_SimP[0][off] + g_SimP[1][off];
    }
    __syncthreads();

    // Phase A: blk; 128 threads -> 2 (r,c) pairs each
#pragma unroll
    for (int p = 0; p < 2; p++) {
        int idx = t + 128 * p;
        int r = idx >> 4, c = idx & 15;
        float bre = 0.f, bim = 0.f;
        for (int i = 0; i < CIN; i++) {
            float sre = sSre[i * KM + r], sim = sSim[i * KM + r];
            size_t widx = (((size_t)i * COUT + o) * KM + r) * KM + c;
            float wre = wr[widx], wim = wi[widx];
            bre = fmaf(sre, wre, bre);  bre = fmaf(-sim, wim, bre);
            bim = fmaf(sre, wim, bim);  bim = fmaf(sim, wre, bim);
        }
        float a = (c == 0 ? 1.0f : 2.0f) * (1.0f / 256.0f);
        bre *= a;
        bim *= a;
        sBq[idx] = make_float4(bre, bre, -bim, bim);
    }
    __syncthreads();

    // Phase B: packed pp[r] = {ReP, ImP} for w0 and w1; shared blk loads
    int w0 = 2 * t, w1 = 2 * t + 1;
    unsigned long long pp0[KM], pp1[KM];
#pragma unroll
    for (int r = 0; r < KM; r++) { pp0[r] = 0ULL; pp1[r] = 0ULL; }
#pragma unroll
    for (int c = 0; c < KM; c++) {
        float s0, c0, s1, c1;
        sincospif((float)(c * w0) / 128.0f, &s0, &c0);
        sincospif((float)(c * w1) / 128.0f, &s1, &c1);
        unsigned long long P1a = pack2(c0, s0), P2a = pack2(s0, c0);
        unsigned long long P1b = pack2(c1, s1), P2b = pack2(s1, c1);
#pragma unroll
        for (int r = 0; r < KM; r++) {
            ulonglong2 bv = *reinterpret_cast<const ulonglong2*>(&sBq[r * KM + c]);
            FMA2(pp0[r], bv.x, P1a, pp0[r]);
            FMA2(pp0[r], bv.y, P2a, pp0[r]);
            FMA2(pp1[r], bv.x, P1b, pp1[r]);
            FMA2(pp1[r], bv.y, P2b, pp1[r]);
        }
    }

    float pre0[KM], pim0[KM], pre1[KM], pim1[KM];
#pragma unroll
    for (int r = 0; r < KM; r++) {
        unpack2(pp0[r], pre0[r], pim0[r]);
        unpack2(pp1[r], pre1[r], pim1[r]);
    }

    unsigned long long* op64 =
        reinterpret_cast<unsigned long long*>(out + (size_t)bo * HH * WW) + t;
    k3_all2(pre0, pim0, pre1, pim1, op64, std::make_integer_sequence<int, 65>{});
}

// ---------------------------------------------------------------------------
extern "C" void kernel_launch(void* const* d_in, const int* in_sizes, int n_in,
                              void* d_out, int out_size) {
    const float* x  = (const float*)d_in[0];
    const float* wr = (const float*)d_in[1];
    const float* wi = (const float*)d_in[2];
    float* out = (float*)d_out;

    k1_S<<<BB * CIN * 2, 256>>>(x);
    k23<<<BB * COUT, 128>>>(wr, wi, out);
}

// round 11
// speedup vs baseline: 1.1931x; 1.1931x over previous
#include <cuda_runtime.h>
#include <utility>

#define HH 256
#define WW 256
#define BB 16
#define CIN 32
#define COUT 32
#define KM 16

// S handoff between k1 and k23 (allocation-free scratch)
__device__ float g_Sre[BB * CIN * KM], g_Sim[BB * CIN * KM];

// Packed f32x2 FMA: d = a*b + c elementwise on {lo,hi} fp32 pairs (FFMA2)
#define FMA2(d, a, b, c) \
    asm("fma.rn.f32x2 %0, %1, %2, %3;" : "=l"(d) : "l"(a), "l"(b), "l"(c))

__device__ __forceinline__ unsigned long long pack2(float lo, float hi) {
    unsigned long long d;
    asm("mov.b64 %0, {%1, %2};" : "=l"(d) : "f"(lo), "f"(hi));
    return d;
}
__device__ __forceinline__ void unpack2(unsigned long long v, float& lo, float& hi) {
    asm("mov.b64 {%0, %1}, %2;" : "=f"(lo), "=f"(hi) : "l"(v));
}

// ---------------------------------------------------------------------------
// Compile-time trig: cos/sin(pi*m/128), exact integer range reduction +
// deg-15/14 Taylor (err ~1e-11). Become FFMA 32-bit immediates.
// ---------------------------------------------------------------------------
constexpr __host__ __device__ double tp_sin(double x) {
    double x2 = x * x, t = x, s = x;
    t *= -x2 / 6.0;   s += t;
    t *= -x2 / 20.0;  s += t;
    t *= -x2 / 42.0;  s += t;
    t *= -x2 / 72.0;  s += t;
    t *= -x2 / 110.0; s += t;
    t *= -x2 / 156.0; s += t;
    t *= -x2 / 210.0; s += t;
    return s;
}
constexpr __host__ __device__ double tp_cos(double x) {
    double x2 = x * x, t = 1.0, s = 1.0;
    t *= -x2 / 2.0;   s += t;
    t *= -x2 / 12.0;  s += t;
    t *= -x2 / 30.0;  s += t;
    t *= -x2 / 56.0;  s += t;
    t *= -x2 / 90.0;  s += t;
    t *= -x2 / 132.0; s += t;
    t *= -x2 / 182.0; s += t;
    return s;
}
constexpr double C_PI = 3.14159265358979323846264338327950288;

constexpr __host__ __device__ float ccosm(int m) {   // cos(pi*m/128)
    m &= 255;
    double sgn = 1.0;
    if (m > 128) m = 256 - m;
    if (m > 64) { sgn = -1.0; m = 128 - m; }
    if (m == 64) return 0.0f;
    return (float)(sgn * tp_cos(C_PI * m / 128.0));
}
constexpr __host__ __device__ float csinm(int m) {   // sin(pi*m/128)
    m &= 255;
    double sgn = 1.0;
    if (m > 128) { sgn = -1.0; m = 256 - m; }
    if (m > 64) m = 128 - m;
    if (m == 0) return 0.0f;
    return (float)(sgn * tp_sin(C_PI * m / 128.0));
}
constexpr __host__ __device__ float cDr(int h) {   // Re D(h)
    double s = 0.0;
    for (int r = 0; r < KM; r++) s += (double)ccosm(r * h);
    return (float)s;
}
constexpr __host__ __device__ float cDi(int h) {   // Im D(h)
    double s = 0.0;
    for (int r = 0; r < KM; r++) s -= (double)csinm(r * h);
    return (float)s;
}

// ---------------------------------------------------------------------------
// K1: block = bc (512 blocks, full 256 rows). Thread (q = t&63, stripe = t>>6)
//   loads float4 at column 4q, rows h = stripe + 4j (j<64). D(h) as FFMA
//   immediates. Cross-stripe reduction through smem, then the 256->16
//   column DFT (unchanged from R8).
// ---------------------------------------------------------------------------
template <int H>
__device__ __forceinline__ void k1s_one(const float4* __restrict__ xq, float* acc) {
    float4 v = xq[H * (WW / 4)];
    constexpr float dr = cDr(H);
    constexpr float di = cDi(H);
    acc[0] = fmaf(v.x, dr, acc[0]);  acc[1] = fmaf(v.x, di, acc[1]);
    acc[2] = fmaf(v.y, dr, acc[2]);  acc[3] = fmaf(v.y, di, acc[3]);
    acc[4] = fmaf(v.z, dr, acc[4]);  acc[5] = fmaf(v.z, di, acc[5]);
    acc[6] = fmaf(v.w, dr, acc[6]);  acc[7] = fmaf(v.w, di, acc[7]);
}
template <int BASE, int... Js>
__device__ __forceinline__ void k1s_all(const float4* __restrict__ xq, float* acc,
                                        std::integer_sequence<int, Js...>) {
    (k1s_one<BASE + 4 * Js>(xq, acc), ...);
}

__global__ __launch_bounds__(256) void k1_S(const float* __restrict__ x) {
    int bc = blockIdx.x;          // b*CIN + c
    int t  = threadIdx.x;         // 0..255
    int q      = t & 63;          // float4 column
    int stripe = t >> 6;          // 0..3

    __shared__ float2 spart[4 * WW];      // [stripe][w] {yre,yim}
    __shared__ float  syre[WW], syim[WW];

    const float4* xq = reinterpret_cast<const float4*>(x + (size_t)bc * HH * WW) + q;
    float acc[8] = {0.f, 0.f, 0.f, 0.f, 0.f, 0.f, 0.f, 0.f};
    using Seq = std::make_integer_sequence<int, HH / 4>;   // 64 rows per stripe
    switch (stripe) {
        case 0: k1s_all<0>(xq, acc, Seq{}); break;
        case 1: k1s_all<1>(xq, acc, Seq{}); break;
        case 2: k1s_all<2>(xq, acc, Seq{}); break;
        default: k1s_all<3>(xq, acc, Seq{}); break;
    }
#pragma unroll
    for (int e = 0; e < 4; e++)
        spart[stripe * WW + 4 * q + e] = make_float2(acc[2 * e], acc[2 * e + 1]);
    __syncthreads();

    {
        int w = t;
        float2 a = spart[0 * WW + w], b2 = spart[1 * WW + w];
        float2 c = spart[2 * WW + w], d2 = spart[3 * WW + w];
        syre[w] = (a.x + b2.x) + (c.x + d2.x);
        syim[w] = (a.y + b2.y) + (c.y + d2.y);
    }
    __syncthreads();

    // 8 warps, each warp handles cols {warp, warp+8}; twiddles on the fly
    int warp = t >> 5, lane = t & 31;
    for (int cc = warp; cc < KM; cc += 8) {
        float are = 0.f, aim = 0.f;
#pragma unroll
        for (int it = 0; it < 8; it++) {
            int j = lane + it * 32;
            float s, c;
            sincospif((float)(cc * j) / 128.0f, &s, &c);
            float yr = syre[j], yi = syim[j];
            are = fmaf(yr, c, are);  are = fmaf(yi, s, are);
            aim = fmaf(yi, c, aim);  aim = fmaf(-yr, s, aim);
        }
#pragma unroll
        for (int off = 16; off; off >>= 1) {
            are += __shfl_down_sync(0xffffffffu, are, off);
            aim += __shfl_down_sync(0xffffffffu, aim, off);
        }
        if (lane == 0) {
            g_Sre[bc * KM + cc] = are * (1.0f / 256.0f);
            g_Sim[bc * KM + cc] = aim * (1.0f / 256.0f);
        }
    }
}

// ---------------------------------------------------------------------------
// K23 phase C body: fully unrolled, trig as FFMA immediates, 4-way h-fold.
// (identical to R8)
// ---------------------------------------------------------------------------
template <int H, int R>
__device__ __forceinline__ void k3_step(const float* pre, const float* pim,
                                        float& Ae, float& Ao, float& Be, float& Bo) {
    constexpr float cv = ccosm(R * H);
    constexpr float sv = csinm(R * H);
    if constexpr ((R & 1) != 0) {
        Ao = fmaf(pre[R], cv, Ao);
        Bo = fmaf(pim[R], sv, Bo);
    } else {
        Ae = fmaf(pre[R], cv, Ae);
        Be = fmaf(pim[R], sv, Be);
    }
}
template <int H, int... Rs>
__device__ __forceinline__ void k3_one(const float* pre, const float* pim,
                                       float* __restrict__ op,
                                       std::integer_sequence<int, Rs...>) {
    float Ae = 0.f, Ao = 0.f, Be = 0.f, Bo = 0.f;
    (k3_step<H, Rs>(pre, pim, Ae, Ao, Be, Bo), ...);
    float Apl = Ae + Ao, Ami = Ae - Ao;
    float Bpl = Be + Bo, Bmi = Be - Bo;
    op[(size_t)H * WW] = Apl - Bpl;
    if constexpr (H != 64)           op[(size_t)(128 - H) * WW] = Ami + Bmi;
    if constexpr (H >= 1)            op[(size_t)(256 - H) * WW] = Apl + Bpl;
    if constexpr (H >= 1 && H != 64) op[(size_t)(128 + H) * WW] = Ami - Bmi;
}
template <int... Hs>
__device__ __forceinline__ void k3_all(const float* pre, const float* pim,
                                       float* __restrict__ op,
                                       std::integer_sequence<int, Hs...>) {
    (k3_one<Hs>(pre, pim, op, std::make_integer_sequence<int, KM>{}), ...);
}

// ---------------------------------------------------------------------------
// K23 (fused, R8 shape): block = bo, 256 threads, 4 CTAs/SM.
//   Phase A: blk[r,c] (pointer-strided weight walk, unroll-4 for L2 MLP).
//   Phase B: packed {ReP,ImP}; twiddles by complex recurrence (1 sincospif).
//   Phase C: fully unrolled immediate-trig inverse h-DFT with 4-way fold.
// ---------------------------------------------------------------------------
__global__ __launch_bounds__(256, 4) void k23(const float* __restrict__ wr,
                                              const float* __restrict__ wi,
                                              float* __restrict__ out) {
    int bo = blockIdx.x;       // b*COUT + o
    int b  = bo >> 5, o = bo & 31;
    int t  = threadIdx.x;      // 0..255

    __shared__ float  sSre[CIN * KM], sSim[CIN * KM];  // [i][r]
    __shared__ float4 sBq[KM * KM];                    // [r][c] {bre,bre,-bim,bim}

    for (int idx = t; idx < CIN * KM; idx += 256) {
        sSre[idx] = g_Sre[b * CIN * KM + idx];
        sSim[idx] = g_Sim[b * CIN * KM + idx];
    }
    __syncthreads();

    // Phase A: blk, thread = r*16 + c; weight i-stride = COUT*KM*KM
    {
        int r = t >> 4, c = t & 15;
        const float* pr = wr + ((size_t)o * KM + r) * KM + c;
        const float* pi = wi + ((size_t)o * KM + r) * KM + c;
        float bre = 0.f, bim = 0.f;
#pragma unroll 4
        for (int i = 0; i < CIN; i++) {
            float sre = sSre[i * KM + r], sim = sSim[i * KM + r];
            float wre = pr[(size_t)i * (COUT * KM * KM)];
            float wim = pi[(size_t)i * (COUT * KM * KM)];
            bre = fmaf(sre, wre, bre);  bre = fmaf(-sim, wim, bre);
            bim = fmaf(sre, wim, bim);  bim = fmaf(sim, wre, bim);
        }
        float a = (c == 0 ? 1.0f : 2.0f) * (1.0f / 256.0f);
        bre *= a;
        bim *= a;
        sBq[t] = make_float4(bre, bre, -bim, bim);
    }
    __syncthreads();

    // Phase B: packed pp[r] = {ReP, ImP}; twiddle by complex recurrence
    int w = t;
    unsigned long long pp[KM];
#pragma unroll
    for (int r = 0; r < KM; r++) pp[r] = 0ULL;

    float s1, c1;
    sincospif((float)w / 128.0f, &s1, &c1);   // e^{+i*pi*w/128}
    float tc = 1.0f, ts = 0.0f;               // twiddle for c = 0
#pragma unroll
    for (int c = 0; c < KM; c++) {
        unsigned long long P1 = pack2(tc, ts);   // {tc, ts}
        unsigned long long P2 = pack2(ts, tc);   // {ts, tc}
#pragma unroll
        for (int r = 0; r < KM; r++) {
            ulonglong2 bv = *reinterpret_cast<const ulonglong2*>(&sBq[r * KM + c]);
            // {pre,pim} += {bre,bre}*{tc,ts}  then  += {-bim,bim}*{ts,tc}
            FMA2(pp[r], bv.x, P1, pp[r]);
            FMA2(pp[r], bv.y, P2, pp[r]);
        }
        // tw <- tw * e^{i*pi*w/128}
        float ntc = fmaf(tc, c1, -ts * s1);
        float nts = fmaf(tc, s1,  ts * c1);
        tc = ntc;
        ts = nts;
    }

    // Unpack to scalar register arrays for the immediate-FFMA phase C
    float pre[KM], pim[KM];
#pragma unroll
    for (int r = 0; r < KM; r++) unpack2(pp[r], pre[r], pim[r]);

    float* op = out + (size_t)bo * HH * WW + w;
    k3_all(pre, pim, op, std::make_integer_sequence<int, 65>{});
}

// ---------------------------------------------------------------------------
extern "C" void kernel_launch(void* const* d_in, const int* in_sizes, int n_in,
                              void* d_out, int out_size) {
    const float* x  = (const float*)d_in[0];
    const float* wr = (const float*)d_in[1];
    const float* wi = (const float*)d_in[2];
    float* out = (float*)d_out;

    k1_S<<<BB * CIN, 256>>>(x);
    k23<<<BB * COUT, 256>>>(wr, wi, out);
}